// round 7
// baseline (speedup 1.0000x reference)
#include <cuda_runtime.h>
#include <cuda_fp16.h>
#include <math.h>
#include <stdint.h>

#define BB 4
#define SS 1024
#define DD 1024
#define HH 16
#define DHH 64
#define FFD 4096
#define LL 4
#define PP 1024
#define SPAN_ 512
#define BS (BB*SS)

typedef long long ll;
typedef __half hf;

// ---------------- scratch ------------------------------------------------------
__device__ float g_h [BS*DD];
__device__ float g_t2[BS*DD];

__device__ hf hb   [BS*DD];
__device__ hf qb   [BS*DD];
__device__ hf kb   [BS*DD];
__device__ hf vb   [BS*DD];
__device__ hf cxb  [BS*DD];
__device__ hf ffb  [(size_t)BS*FFD];
__device__ hf rlb  [PP*DD];
__device__ hf pkb  [PP*DD];
__device__ hf pqb  [PP*DD];
__device__ hf wqt  [DD*DD];
__device__ hf wkt  [DD*DD];
__device__ hf wvt  [DD*DD];
__device__ hf wot  [DD*DD];
__device__ hf w1t  [(size_t)FFD*DD];
__device__ hf w2t  [(size_t)DD*FFD];
__device__ hf vtb  [(size_t)BB*HH*DHH*SS];
__device__ hf prb  [(size_t)BB*HH*SS*SS];
__device__ hf s1b  [(size_t)BB*HH*SS*SS];
__device__ hf c2pb [(size_t)BB*HH*SS*PP];
__device__ hf p2cb [(size_t)BB*HH*SS*PP];
__device__ hf p2cTb[(size_t)BB*HH*SS*SS];

// ---------------- helpers ------------------------------------------------------
__device__ __forceinline__ uint32_t smem_u32(const void* p) {
    uint32_t a;
    asm("{ .reg .u64 t; cvta.to.shared.u64 t, %1; cvt.u32.u64 %0, t; }" : "=r"(a) : "l"(p));
    return a;
}
__device__ __forceinline__ void cpa16(uint32_t dst, const void* src) {
    asm volatile("cp.async.cg.shared.global [%0], [%1], 16;" :: "r"(dst), "l"(src));
}
__device__ __forceinline__ void cpa_commit() { asm volatile("cp.async.commit_group;" ::: "memory"); }

__device__ __forceinline__ void ldm4(uint32_t* r, uint32_t addr) {
    asm volatile("ldmatrix.sync.aligned.m8n8.x4.shared.b16 {%0,%1,%2,%3}, [%4];"
                 : "=r"(r[0]), "=r"(r[1]), "=r"(r[2]), "=r"(r[3]) : "r"(addr));
}
__device__ __forceinline__ void mma16816(float* d, const uint32_t* a, const uint32_t* b) {
    asm volatile("mma.sync.aligned.m16n8k16.row.col.f32.f16.f16.f32 "
                 "{%0,%1,%2,%3}, {%4,%5,%6,%7}, {%8,%9}, {%0,%1,%2,%3};"
                 : "+f"(d[0]), "+f"(d[1]), "+f"(d[2]), "+f"(d[3])
                 : "r"(a[0]), "r"(a[1]), "r"(a[2]), "r"(a[3]), "r"(b[0]), "r"(b[1]));
}

// ---------------- fp16 mma.sync GEMM, 3-stage pipeline ---------------------------
// C[128 x NT] tile per block. A rows [m][k], B rows [n][k] (k-contiguous).
// z decodes (b = z>>4, h = z&15) for batched strides.
template <int NT, int ACT>
__global__ void __launch_bounds__(256) gemm_mma(
    const hf* __restrict__ A, int ldA, ll aSB, ll aSH,
    const hf* __restrict__ B, int ldB, ll bSB, ll bSH,
    float* __restrict__ C, hf* __restrict__ Ch,
    int ldC, ll cSB, ll cSH,
    int K, const float* __restrict__ bias)
{
    constexpr int ABY = 128 * 128;          // bytes: 128 rows x 64 halfs
    constexpr int BBY = NT * 128;
    constexpr int STAGE = ABY + BBY;
    constexpr int MT = (NT == 256) ? 4 : 2; // 16-row m-tiles per warp
    constexpr int JT = (NT == 256) ? 8 : 4; // 8-col n-subtiles per warp

    extern __shared__ char smem_raw[];
    uint32_t sbase = smem_u32(smem_raw);

    int tid = threadIdx.x, lane = tid & 31, wid = tid >> 5;
    int z = blockIdx.z;

    int warpM, warpN;
    if (NT == 256) { warpM = (wid & 1) * 64; warpN = (wid >> 1) * 64; }
    else           { warpM = (wid & 3) * 32; warpN = (wid >> 2) * 32; }

    const hf* Ab = A + (size_t)((ll)(z >> 4) * aSB + (ll)(z & 15) * aSH)
                     + (size_t)blockIdx.y * 128 * ldA;
    const hf* Bb = B + (size_t)((ll)(z >> 4) * bSB + (ll)(z & 15) * bSH)
                     + (size_t)blockIdx.x * NT * ldB;

    int NC = K >> 6;

    auto load_chunk = [&](int cn, int stage) {
        const hf* Ap = Ab + cn * 64;
        const hf* Bp = Bb + cn * 64;
        uint32_t Ad = sbase + stage * STAGE;
        uint32_t Bd = Ad + ABY;
        #pragma unroll
        for (int i = 0; i < 4; i++) {
            int idx = tid + i * 256;
            int r = idx >> 3, c = idx & 7;
            cpa16(Ad + r * 128 + ((c ^ (r & 7)) << 4), Ap + (size_t)r * ldA + c * 8);
        }
        #pragma unroll
        for (int i = 0; i < NT / 32; i++) {
            int idx = tid + i * 256;
            int r = idx >> 3, c = idx & 7;
            cpa16(Bd + r * 128 + ((c ^ (r & 7)) << 4), Bp + (size_t)r * ldB + c * 8);
        }
        cpa_commit();
    };

    float acc[MT][JT][4];
    #pragma unroll
    for (int i = 0; i < MT; i++)
        #pragma unroll
        for (int j = 0; j < JT; j++)
            #pragma unroll
            for (int e = 0; e < 4; e++) acc[i][j][e] = 0.f;

    load_chunk(0, 0);
    if (NC > 1) load_chunk(1, 1);

    for (int c = 0; c < NC; c++) {
        if (c + 1 < NC) asm volatile("cp.async.wait_group 1;" ::: "memory");
        else            asm volatile("cp.async.wait_group 0;" ::: "memory");
        __syncthreads();

        uint32_t Abuf = sbase + (c % 3) * STAGE;
        uint32_t Bbuf = Abuf + ABY;
        #pragma unroll
        for (int ks = 0; ks < 4; ks++) {
            uint32_t a[MT][4], b[JT][2];
            #pragma unroll
            for (int i = 0; i < MT; i++) {
                int row = warpM + i * 16 + (lane & 15);
                int cc = ks * 2 + (lane >> 4);
                ldm4(a[i], Abuf + row * 128 + (((cc ^ (row & 7)) << 4)));
            }
            #pragma unroll
            for (int j = 0; j < JT / 2; j++) {
                int n = warpN + j * 16 + ((lane >> 4) << 3) + (lane & 7);
                int cc = ks * 2 + ((lane >> 3) & 1);
                uint32_t t[4];
                ldm4(t, Bbuf + n * 128 + (((cc ^ (n & 7)) << 4)));
                b[j*2][0] = t[0];   b[j*2][1] = t[1];
                b[j*2+1][0] = t[2]; b[j*2+1][1] = t[3];
            }
            #pragma unroll
            for (int i = 0; i < MT; i++)
                #pragma unroll
                for (int j = 0; j < JT; j++)
                    mma16816(acc[i][j], a[i], b[j]);
        }
        if (c + 2 < NC) load_chunk(c + 2, (c + 2) % 3);
    }

    // ---- epilogue ----
    ll cO = (ll)(z >> 4) * cSB + (ll)(z & 15) * cSH;
    int m0 = blockIdx.y * 128, n0 = blockIdx.x * NT;
    int quad = lane >> 2, l4 = lane & 3;

    #pragma unroll
    for (int i = 0; i < MT; i++) {
        int r0 = m0 + warpM + i * 16 + quad;
        #pragma unroll
        for (int j = 0; j < JT; j++) {
            int col = n0 + warpN + j * 8 + l4 * 2;
            float b0 = 0.f, b1 = 0.f;
            if (bias) { b0 = bias[col]; b1 = bias[col + 1]; }
            #pragma unroll
            for (int half = 0; half < 2; half++) {
                int row = r0 + half * 8;
                float v0 = acc[i][j][half*2 + 0] + b0;
                float v1 = acc[i][j][half*2 + 1] + b1;
                if (ACT) {
                    v0 = 0.5f * v0 * (1.f + erff(v0 * 0.70710678118654752f));
                    v1 = 0.5f * v1 * (1.f + erff(v1 * 0.70710678118654752f));
                }
                size_t base = (size_t)cO + (size_t)row * ldC + col;
                if (C) *(float2*)(C + base) = make_float2(v0, v1);
                if (Ch) *(__half2*)(Ch + base) =
                    __halves2half2(__float2half(v0), __float2half(v1));
            }
        }
    }
}

// ---------------- converters -----------------------------------------------------
__global__ __launch_bounds__(256) void cvt_fp16(
    const float* __restrict__ in, hf* __restrict__ out, size_t n)
{
    for (size_t i = blockIdx.x * 256ull + threadIdx.x; i < n; i += gridDim.x * 256ull)
        out[i] = __float2half(in[i]);
}

// in [K x N] fp32 -> out [N x K] fp16
__global__ void transpose_cvt(
    const float* __restrict__ in, hf* __restrict__ out, int K, int N)
{
    __shared__ float t[32][33];
    int k0 = blockIdx.y * 32, n0 = blockIdx.x * 32;
    int tx = threadIdx.x, ty = threadIdx.y;
    for (int i = ty; i < 32; i += 8)
        t[i][tx] = in[(size_t)(k0 + i) * N + n0 + tx];
    __syncthreads();
    for (int i = ty; i < 32; i += 8)
        out[(size_t)(n0 + i) * K + k0 + tx] = __float2half(t[tx][i]);
}

// v fp16 [b][s][h*64+d] -> vt fp16 [(b*16+h)*64+d][s]
__global__ void vt_cvt(const hf* __restrict__ v, hf* __restrict__ out)
{
    __shared__ hf t[32][33];
    int bh = blockIdx.z, b = bh >> 4, h = bh & 15;
    int s0 = blockIdx.x * 32, d0 = blockIdx.y * 32;
    int tx = threadIdx.x, ty = threadIdx.y;
    for (int i = ty; i < 32; i += 8)
        t[i][tx] = v[((size_t)b * SS + s0 + i) * DD + h * 64 + d0 + tx];
    __syncthreads();
    for (int i = ty; i < 32; i += 8)
        out[((size_t)bh * 64 + d0 + i) * SS + s0 + tx] = t[tx][i];
}

// p2cT[bh][q][k] = p2c[bh][k][clip(q-k+512,0,1023)]
__global__ void p2c_remap(const hf* __restrict__ p2c, hf* __restrict__ out)
{
    __shared__ hf t[64][34];
    int bh = blockIdx.z;
    int q0 = blockIdx.y * 32, k0 = blockIdx.x * 32;
    int tx = threadIdx.x, ty = threadIdx.y;
    int base = q0 - k0 + SPAN_ - 31;
    const hf* src = p2c + (size_t)bh * SS * PP;
    for (int kk = ty; kk < 32; kk += 8) {
        int row = k0 + kk;
        int c0 = min(max(base + tx, 0), PP - 1);
        int c1 = min(max(base + tx + 32, 0), PP - 1);
        t[tx][kk]      = src[(size_t)row * PP + c0];
        t[tx + 32][kk] = src[(size_t)row * PP + c1];
    }
    __syncthreads();
    hf* dst = out + (size_t)bh * SS * SS;
    for (int qq = ty; qq < 32; qq += 8)
        dst[(size_t)(q0 + qq) * SS + k0 + tx] = t[qq + 31 - tx][tx];
}

// ---------------- embedding / LN / softmax ----------------------------------------
__global__ __launch_bounds__(256) void embed_ln(
    const int* __restrict__ ids, const int* __restrict__ segs,
    const float* __restrict__ mask, const float* __restrict__ tok,
    const float* __restrict__ seg, const float* __restrict__ g,
    const float* __restrict__ b)
{
    int row = blockIdx.x, tid = threadIdx.x;
    const float* t  = tok + (size_t)ids[row]  * DD;
    const float* sg = seg + (size_t)segs[row] * DD;
    float x[4]; float s = 0.f;
    #pragma unroll
    for (int i = 0; i < 4; i++) { int c = tid + i*256; x[i] = t[c] + sg[c]; s += x[i]; }
    __shared__ float red[256];
    red[tid] = s; __syncthreads();
    for (int o = 128; o > 0; o >>= 1) { if (tid < o) red[tid] += red[tid+o]; __syncthreads(); }
    float m = red[0] * (1.f / DD); __syncthreads();
    s = 0.f;
    #pragma unroll
    for (int i = 0; i < 4; i++) { float d = x[i] - m; s += d*d; }
    red[tid] = s; __syncthreads();
    for (int o = 128; o > 0; o >>= 1) { if (tid < o) red[tid] += red[tid+o]; __syncthreads(); }
    float inv = rsqrtf(red[0] * (1.f / DD) + 1e-12f);
    float mk = mask[row];
    #pragma unroll
    for (int i = 0; i < 4; i++) {
        int c = tid + i*256;
        float y = ((x[i] - m) * inv * g[c] + b[c]) * mk;
        size_t o = (size_t)row * DD + c;
        g_h[o] = y; hb[o] = __float2half(y);
    }
}

__global__ __launch_bounds__(256) void add_ln(
    const float* __restrict__ base, const float* __restrict__ addv,
    const float* __restrict__ g, const float* __restrict__ b,
    float* __restrict__ out)
{
    int row = blockIdx.x, tid = threadIdx.x;
    size_t off = (size_t)row * DD;
    float x[4]; float s = 0.f;
    #pragma unroll
    for (int i = 0; i < 4; i++) { int c = tid + i*256; x[i] = base[off+c] + addv[off+c]; s += x[i]; }
    __shared__ float red[256];
    red[tid] = s; __syncthreads();
    for (int o = 128; o > 0; o >>= 1) { if (tid < o) red[tid] += red[tid+o]; __syncthreads(); }
    float m = red[0] * (1.f / DD); __syncthreads();
    s = 0.f;
    #pragma unroll
    for (int i = 0; i < 4; i++) { float d = x[i] - m; s += d*d; }
    red[tid] = s; __syncthreads();
    for (int o = 128; o > 0; o >>= 1) { if (tid < o) red[tid] += red[tid+o]; __syncthreads(); }
    float inv = rsqrtf(red[0] * (1.f / DD) + 1e-12f);
    #pragma unroll
    for (int i = 0; i < 4; i++) {
        int c = tid + i*256;
        float y = (x[i] - m) * inv * g[c] + b[c];
        out[off + c] = y; hb[off + c] = __float2half(y);
    }
}

__global__ __launch_bounds__(256) void softmax_rel(
    const hf* __restrict__ att, const hf* __restrict__ c2p,
    const hf* __restrict__ p2cT, const float* __restrict__ mask)
{
    int bh = blockIdx.y, q = blockIdx.x, b = bh / HH;
    int tid = threadIdx.x;
    size_t rowOff = ((size_t)bh * SS + q) * SS;
    const float scale = 0.07216878364870323f; // 1/sqrt(64*3)

    float v[4];
    #pragma unroll
    for (int t = 0; t < 4; t++) {
        int k = tid + t * 256;
        int idx = min(max(q - k + SPAN_, 0), PP - 1);
        float s = __half2float(att[rowOff + k])
                + __half2float(c2p[((size_t)bh * SS + q) * PP + idx])
                + __half2float(p2cT[rowOff + k]);
        v[t] = s * scale + (1.f - mask[b * SS + k]) * -1e9f;
    }
    __shared__ float red[256];
    float m = fmaxf(fmaxf(v[0], v[1]), fmaxf(v[2], v[3]));
    red[tid] = m; __syncthreads();
    for (int o = 128; o > 0; o >>= 1) { if (tid < o) red[tid] = fmaxf(red[tid], red[tid+o]); __syncthreads(); }
    m = red[0]; __syncthreads();
    float s = 0.f;
    #pragma unroll
    for (int t = 0; t < 4; t++) { v[t] = expf(v[t] - m); s += v[t]; }
    red[tid] = s; __syncthreads();
    for (int o = 128; o > 0; o >>= 1) { if (tid < o) red[tid] += red[tid+o]; __syncthreads(); }
    float inv = 1.f / red[0];
    #pragma unroll
    for (int t = 0; t < 4; t++)
        prb[rowOff + tid + t * 256] = __float2half(v[t] * inv);
}

// ---------------- host --------------------------------------------------------------
extern "C" void kernel_launch(void* const* d_in, const int* in_sizes, int n_in,
                              void* d_out, int out_size)
{
    const int*   ids  = (const int*)d_in[0];
    const int*   segs = (const int*)d_in[1];
    const float* mask = (const float*)d_in[2];
    const float* tok  = (const float*)d_in[3];
    const float* seg  = (const float*)d_in[4];
    const float* elg  = (const float*)d_in[5];
    const float* elb  = (const float*)d_in[6];
    const float* rel  = (const float*)d_in[7];
    const float* Wq = (const float*)d_in[8],  *bq = (const float*)d_in[9];
    const float* Wk = (const float*)d_in[10], *bk = (const float*)d_in[11];
    const float* Wv = (const float*)d_in[12], *bv = (const float*)d_in[13];
    const float* Wo = (const float*)d_in[14], *bo = (const float*)d_in[15];
    const float* l1g = (const float*)d_in[16], *l1b = (const float*)d_in[17];
    const float* W1 = (const float*)d_in[18], *b1 = (const float*)d_in[19];
    const float* W2 = (const float*)d_in[20], *b2 = (const float*)d_in[21];
    const float* l2g = (const float*)d_in[22], *l2b = (const float*)d_in[23];

    float *h, *t2;
    cudaGetSymbolAddress((void**)&h,  g_h);
    cudaGetSymbolAddress((void**)&t2, g_t2);

    hf *hh,*q,*k,*v,*cx,*ff,*rl,*pk,*pq;
    hf *wq_,*wk_,*wv_,*wo_,*w1_,*w2_;
    hf *vt,*pr,*s1,*c2p,*p2c,*p2cT;
    cudaGetSymbolAddress((void**)&hh, hb);
    cudaGetSymbolAddress((void**)&q,  qb);    cudaGetSymbolAddress((void**)&k,  kb);
    cudaGetSymbolAddress((void**)&v,  vb);    cudaGetSymbolAddress((void**)&cx, cxb);
    cudaGetSymbolAddress((void**)&ff, ffb);   cudaGetSymbolAddress((void**)&rl, rlb);
    cudaGetSymbolAddress((void**)&pk, pkb);   cudaGetSymbolAddress((void**)&pq, pqb);
    cudaGetSymbolAddress((void**)&wq_, wqt);  cudaGetSymbolAddress((void**)&wk_, wkt);
    cudaGetSymbolAddress((void**)&wv_, wvt);  cudaGetSymbolAddress((void**)&wo_, wot);
    cudaGetSymbolAddress((void**)&w1_, w1t);  cudaGetSymbolAddress((void**)&w2_, w2t);
    cudaGetSymbolAddress((void**)&vt, vtb);   cudaGetSymbolAddress((void**)&pr, prb);
    cudaGetSymbolAddress((void**)&s1, s1b);   cudaGetSymbolAddress((void**)&c2p, c2pb);
    cudaGetSymbolAddress((void**)&p2c, p2cb); cudaGetSymbolAddress((void**)&p2cT, p2cTb);

    const int SM256 = 3 * (128*128 + 256*128);   // 147456
    const int SM64  = 3 * (128*128 + 64*128);    // 73728
    cudaFuncSetAttribute(gemm_mma<256,0>, cudaFuncAttributeMaxDynamicSharedMemorySize, SM256);
    cudaFuncSetAttribute(gemm_mma<256,1>, cudaFuncAttributeMaxDynamicSharedMemorySize, SM256);
    cudaFuncSetAttribute(gemm_mma<64,0>,  cudaFuncAttributeMaxDynamicSharedMemorySize, SM64);

    embed_ln<<<BS, 256>>>(ids, segs, mask, tok, seg, elg, elb);
    cvt_fp16<<<512, 256>>>(rel, rl, (size_t)PP * DD);

    dim3 tb(32, 8);
    const ll S2 = (ll)SS * SS;
    const ll SD = (ll)SS * DD;

    for (int l = 0; l < LL; l++) {
        const float* wq = Wq + (size_t)l*DD*DD;  const float* bq_ = bq + (size_t)l*DD;
        const float* wk = Wk + (size_t)l*DD*DD;  const float* bk_ = bk + (size_t)l*DD;
        const float* wv = Wv + (size_t)l*DD*DD;  const float* bv_ = bv + (size_t)l*DD;
        const float* wo = Wo + (size_t)l*DD*DD;  const float* bo_ = bo + (size_t)l*DD;
        const float* w1 = W1 + (size_t)l*DD*FFD; const float* b1_ = b1 + (size_t)l*FFD;
        const float* w2 = W2 + (size_t)l*FFD*DD; const float* b2_ = b2 + (size_t)l*DD;
        const float* g1 = l1g + (size_t)l*DD;    const float* be1 = l1b + (size_t)l*DD;
        const float* g2 = l2g + (size_t)l*DD;    const float* be2 = l2b + (size_t)l*DD;

        transpose_cvt<<<dim3(32, 32),  tb>>>(wq, wq_, DD, DD);
        transpose_cvt<<<dim3(32, 32),  tb>>>(wk, wk_, DD, DD);
        transpose_cvt<<<dim3(32, 32),  tb>>>(wv, wv_, DD, DD);
        transpose_cvt<<<dim3(32, 32),  tb>>>(wo, wo_, DD, DD);
        transpose_cvt<<<dim3(128, 32), tb>>>(w1, w1_, DD, FFD);
        transpose_cvt<<<dim3(32, 128), tb>>>(w2, w2_, FFD, DD);

        // projections (NT=256)
        gemm_mma<256,0><<<dim3(4,32,1), 256, SM256>>>(hh,DD,0,0, wq_,DD,0,0,
            (float*)0, q, DD,0,0, DD, bq_);
        gemm_mma<256,0><<<dim3(4,32,1), 256, SM256>>>(hh,DD,0,0, wk_,DD,0,0,
            (float*)0, k, DD,0,0, DD, bk_);
        gemm_mma<256,0><<<dim3(4,32,1), 256, SM256>>>(hh,DD,0,0, wv_,DD,0,0,
            (float*)0, v, DD,0,0, DD, bv_);
        gemm_mma<256,0><<<dim3(4,8,1),  256, SM256>>>(rl,DD,0,0, wk_,DD,0,0,
            (float*)0, pk, DD,0,0, DD, bk_);
        gemm_mma<256,0><<<dim3(4,8,1),  256, SM256>>>(rl,DD,0,0, wq_,DD,0,0,
            (float*)0, pq, DD,0,0, DD, bq_);

        // attention scores (NT=256)
        gemm_mma<256,0><<<dim3(4,8,64), 256, SM256>>>(q,DD,SD,64, k,DD,SD,64,
            (float*)0, s1, SS,16*S2,S2, 64, (const float*)0);
        gemm_mma<256,0><<<dim3(4,8,64), 256, SM256>>>(q,DD,SD,64, pk,DD,0,64,
            (float*)0, c2p, PP,16*S2,S2, 64, (const float*)0);
        gemm_mma<256,0><<<dim3(4,8,64), 256, SM256>>>(k,DD,SD,64, pq,DD,0,64,
            (float*)0, p2c, PP,16*S2,S2, 64, (const float*)0);

        p2c_remap<<<dim3(32,32,64), tb>>>(p2c, p2cT);
        softmax_rel<<<dim3(SS, 64), 256>>>(s1, c2p, p2cT, mask);
        vt_cvt<<<dim3(32,2,64), tb>>>(v, vt);

        // ctx = probs @ V (NT=64)
        gemm_mma<64,0><<<dim3(1,8,64), 256, SM64>>>(pr,SS,16*S2,S2, vt,SS,(ll)16*64*SS,(ll)64*SS,
            (float*)0, cx, DD,SD,64, SS, (const float*)0);

        // output projection + LN
        gemm_mma<256,0><<<dim3(4,32,1), 256, SM256>>>(cx,DD,0,0, wo_,DD,0,0,
            t2, (hf*)0, DD,0,0, DD, bo_);
        add_ln<<<BS, 256>>>(h, t2, g1, be1, h);

        // FFN
        gemm_mma<256,1><<<dim3(16,32,1), 256, SM256>>>(hh,DD,0,0, w1_,DD,0,0,
            (float*)0, ff, FFD,0,0, DD, b1_);
        gemm_mma<256,0><<<dim3(4,32,1), 256, SM256>>>(ff,FFD,0,0, w2_,FFD,0,0,
            t2, (hf*)0, DD,0,0, FFD, b2_);
        add_ln<<<BS, 256>>>(h, t2, g2, be2, h);
    }

    cudaMemcpyAsync(d_out, h, (size_t)BS * DD * sizeof(float),
                    cudaMemcpyDeviceToDevice);
}

// round 9
// speedup vs baseline: 1.1373x; 1.1373x over previous
#include <cuda_runtime.h>
#include <cuda_fp16.h>
#include <math.h>
#include <stdint.h>

#define BB 4
#define SS 1024
#define DD 1024
#define HH 16
#define DHH 64
#define FFD 4096
#define LL 4
#define PP 1024
#define SPAN_ 512
#define BS (BB*SS)

typedef long long ll;
typedef __half hf;

// ---------------- scratch ------------------------------------------------------
__device__ float g_h [BS*DD];
__device__ float g_t2[BS*DD];
__device__ float qkv_bias[3*DD];
__device__ float pos_bias[2*DD];

__device__ hf hb    [BS*DD];
__device__ hf qkvb  [(size_t)BS*3*DD];     // q | k | v per row
__device__ hf cxb   [BS*DD];
__device__ hf ffb   [(size_t)BS*FFD];
__device__ hf rlb   [PP*DD];
__device__ hf posb  [(size_t)PP*2*DD];     // pos_k | pos_q per row
__device__ hf wqkvt [(size_t)3*DD*DD];
__device__ hf wpost [(size_t)2*DD*DD];
__device__ hf wot   [DD*DD];
__device__ hf w1t   [(size_t)FFD*DD];
__device__ hf w2t   [(size_t)DD*FFD];
__device__ hf vtb   [(size_t)BB*HH*DHH*SS];
__device__ hf prb   [(size_t)BB*HH*SS*SS];
__device__ hf s1b   [(size_t)BB*HH*SS*SS];
__device__ hf c2pb  [(size_t)BB*HH*SS*PP];
__device__ hf p2cb  [(size_t)BB*HH*SS*PP];
__device__ hf p2cTb [(size_t)BB*HH*SS*SS];

// ---------------- helpers ------------------------------------------------------
__device__ __forceinline__ uint32_t smem_u32(const void* p) {
    uint32_t a;
    asm("{ .reg .u64 t; cvta.to.shared.u64 t, %1; cvt.u32.u64 %0, t; }" : "=r"(a) : "l"(p));
    return a;
}
__device__ __forceinline__ void cpa16(uint32_t dst, const void* src) {
    asm volatile("cp.async.cg.shared.global [%0], [%1], 16;" :: "r"(dst), "l"(src));
}
__device__ __forceinline__ void cpa_commit() { asm volatile("cp.async.commit_group;" ::: "memory"); }

__device__ __forceinline__ void ldm4(uint32_t* r, uint32_t addr) {
    asm volatile("ldmatrix.sync.aligned.m8n8.x4.shared.b16 {%0,%1,%2,%3}, [%4];"
                 : "=r"(r[0]), "=r"(r[1]), "=r"(r[2]), "=r"(r[3]) : "r"(addr));
}
__device__ __forceinline__ void mma16816(float* d, const uint32_t* a, const uint32_t* b) {
    asm volatile("mma.sync.aligned.m16n8k16.row.col.f32.f16.f16.f32 "
                 "{%0,%1,%2,%3}, {%4,%5,%6,%7}, {%8,%9}, {%0,%1,%2,%3};"
                 : "+f"(d[0]), "+f"(d[1]), "+f"(d[2]), "+f"(d[3])
                 : "r"(a[0]), "r"(a[1]), "r"(a[2]), "r"(a[3]), "r"(b[0]), "r"(b[1]));
}

// ---------------- fp16 mma.sync GEMM, 3-stage, 1 sync/chunk ----------------------
// C[128 x NT] tile per block. A rows [m][k], B rows [n][k] (k-contiguous).
// NT=128: warp tile 64x32 (MT=4). NT=64: warp tile 32x32 (MT=2).
template <int NT, int ACT>
__global__ void __launch_bounds__(256) gemm_mma(
    const hf* __restrict__ A, int ldA, ll aSB, ll aSH,
    const hf* __restrict__ B, int ldB, ll bSB, ll bSH,
    float* __restrict__ C, hf* __restrict__ Ch,
    int ldC, ll cSB, ll cSH,
    int K, const float* __restrict__ bias)
{
    constexpr int ABY = 128 * 128;          // bytes: 128 rows x 64 halfs
    constexpr int BBY = NT * 128;
    constexpr int STAGE = ABY + BBY;
    constexpr int MT = (NT == 128) ? 4 : 2;
    constexpr int JT = 4;

    extern __shared__ char smem_raw[];
    uint32_t sbase = smem_u32(smem_raw);

    int tid = threadIdx.x, lane = tid & 31, wid = tid >> 5;
    int z = blockIdx.z;

    int warpM, warpN;
    if (NT == 128) { warpM = (wid & 1) * 64; warpN = (wid >> 1) * 32; }
    else           { warpM = (wid & 3) * 32; warpN = (wid >> 2) * 32; }

    const hf* Ab = A + (size_t)((ll)(z >> 4) * aSB + (ll)(z & 15) * aSH)
                     + (size_t)blockIdx.y * 128 * ldA;
    const hf* Bb = B + (size_t)((ll)(z >> 4) * bSB + (ll)(z & 15) * bSH)
                     + (size_t)blockIdx.x * NT * ldB;

    int NC = K >> 6;

    auto load_chunk = [&](int cn, int stage) {
        const hf* Ap = Ab + cn * 64;
        const hf* Bp = Bb + cn * 64;
        uint32_t Ad = sbase + stage * STAGE;
        uint32_t Bd = Ad + ABY;
        #pragma unroll
        for (int i = 0; i < 4; i++) {
            int idx = tid + i * 256;
            int r = idx >> 3, c = idx & 7;
            cpa16(Ad + r * 128 + ((c ^ (r & 7)) << 4), Ap + (size_t)r * ldA + c * 8);
        }
        #pragma unroll
        for (int i = 0; i < NT / 32; i++) {
            int idx = tid + i * 256;
            int r = idx >> 3, c = idx & 7;
            cpa16(Bd + r * 128 + ((c ^ (r & 7)) << 4), Bp + (size_t)r * ldB + c * 8);
        }
        cpa_commit();
    };

    float acc[MT][JT][4];
    #pragma unroll
    for (int i = 0; i < MT; i++)
        #pragma unroll
        for (int j = 0; j < JT; j++)
            #pragma unroll
            for (int e = 0; e < 4; e++) acc[i][j][e] = 0.f;

    load_chunk(0, 0);
    if (NC > 1) load_chunk(1, 1);

    for (int c = 0; c < NC; c++) {
        if (c + 1 < NC) asm volatile("cp.async.wait_group 1;" ::: "memory");
        else            asm volatile("cp.async.wait_group 0;" ::: "memory");
        __syncthreads();

        uint32_t Abuf = sbase + (c % 3) * STAGE;
        uint32_t Bbuf = Abuf + ABY;
        #pragma unroll
        for (int ks = 0; ks < 4; ks++) {
            uint32_t a[MT][4], b[JT][2];
            #pragma unroll
            for (int i = 0; i < MT; i++) {
                int row = warpM + i * 16 + (lane & 15);
                int cc = ks * 2 + (lane >> 4);
                ldm4(a[i], Abuf + row * 128 + (((cc ^ (row & 7)) << 4)));
            }
            #pragma unroll
            for (int j = 0; j < JT / 2; j++) {
                int n = warpN + j * 16 + ((lane >> 4) << 3) + (lane & 7);
                int cc = ks * 2 + ((lane >> 3) & 1);
                uint32_t t[4];
                ldm4(t, Bbuf + n * 128 + (((cc ^ (n & 7)) << 4)));
                b[j*2][0] = t[0];   b[j*2][1] = t[1];
                b[j*2+1][0] = t[2]; b[j*2+1][1] = t[3];
            }
            #pragma unroll
            for (int i = 0; i < MT; i++)
                #pragma unroll
                for (int j = 0; j < JT; j++)
                    mma16816(acc[i][j], a[i], b[j]);
        }
        if (c + 2 < NC) load_chunk(c + 2, (c + 2) % 3);
    }

    // ---- epilogue ----
    ll cO = (ll)(z >> 4) * cSB + (ll)(z & 15) * cSH;
    int m0 = blockIdx.y * 128, n0 = blockIdx.x * NT;
    int quad = lane >> 2, l4 = lane & 3;

    #pragma unroll
    for (int i = 0; i < MT; i++) {
        int r0 = m0 + warpM + i * 16 + quad;
        #pragma unroll
        for (int j = 0; j < JT; j++) {
            int col = n0 + warpN + j * 8 + l4 * 2;
            float b0 = 0.f, b1 = 0.f;
            if (bias) { b0 = bias[col]; b1 = bias[col + 1]; }
            #pragma unroll
            for (int half = 0; half < 2; half++) {
                int row = r0 + half * 8;
                float v0 = acc[i][j][half*2 + 0] + b0;
                float v1 = acc[i][j][half*2 + 1] + b1;
                if (ACT) {
                    v0 = 0.5f * v0 * (1.f + erff(v0 * 0.70710678118654752f));
                    v1 = 0.5f * v1 * (1.f + erff(v1 * 0.70710678118654752f));
                }
                size_t base = (size_t)cO + (size_t)row * ldC + col;
                if (C) *(float2*)(C + base) = make_float2(v0, v1);
                if (Ch) *(__half2*)(Ch + base) =
                    __halves2half2(__float2half(v0), __float2half(v1));
            }
        }
    }
}

// ---------------- converters -----------------------------------------------------
__global__ __launch_bounds__(256) void cvt_fp16(
    const float* __restrict__ in, hf* __restrict__ out, size_t n)
{
    for (size_t i = blockIdx.x * 256ull + threadIdx.x; i < n; i += gridDim.x * 256ull)
        out[i] = __float2half(in[i]);
}

__global__ void concat_bias(const float* a, const float* b, const float* c,
                            float* out2, float* out3)
{
    int i = blockIdx.x * 256 + threadIdx.x;
    if (i < DD) {
        out3[i] = a[i]; out3[i + DD] = b[i]; out3[i + 2*DD] = c[i];
        out2[i] = b[i]; out2[i + DD] = a[i];       // pos order: (bk, bq)
    }
}

// in [K x N] fp32 -> out [N x K] fp16
__global__ void transpose_cvt(
    const float* __restrict__ in, hf* __restrict__ out, int K, int N)
{
    __shared__ float t[32][33];
    int k0 = blockIdx.y * 32, n0 = blockIdx.x * 32;
    int tx = threadIdx.x, ty = threadIdx.y;
    for (int i = ty; i < 32; i += 8)
        t[i][tx] = in[(size_t)(k0 + i) * N + n0 + tx];
    __syncthreads();
    for (int i = ty; i < 32; i += 8)
        out[(size_t)(n0 + i) * K + k0 + tx] = __float2half(t[tx][i]);
}

// v fp16 (rows stride ldv) [b][s][h*64+d] -> vt fp16 [(b*16+h)*64+d][s]
__global__ void vt_cvt(const hf* __restrict__ v, int ldv, hf* __restrict__ out)
{
    __shared__ hf t[32][33];
    int bh = blockIdx.z, b = bh >> 4, h = bh & 15;
    int s0 = blockIdx.x * 32, d0 = blockIdx.y * 32;
    int tx = threadIdx.x, ty = threadIdx.y;
    for (int i = ty; i < 32; i += 8)
        t[i][tx] = v[((size_t)b * SS + s0 + i) * ldv + h * 64 + d0 + tx];
    __syncthreads();
    for (int i = ty; i < 32; i += 8)
        out[((size_t)bh * 64 + d0 + i) * SS + s0 + tx] = t[tx][i];
}

// p2cT[bh][q][k] = p2c[bh][k][clip(q-k+512,0,1023)]
__global__ void p2c_remap(const hf* __restrict__ p2c, hf* __restrict__ out)
{
    __shared__ hf t[64][34];
    int bh = blockIdx.z;
    int q0 = blockIdx.y * 32, k0 = blockIdx.x * 32;
    int tx = threadIdx.x, ty = threadIdx.y;
    int base = q0 - k0 + SPAN_ - 31;
    const hf* src = p2c + (size_t)bh * SS * PP;
    for (int kk = ty; kk < 32; kk += 8) {
        int row = k0 + kk;
        int c0 = min(max(base + tx, 0), PP - 1);
        int c1 = min(max(base + tx + 32, 0), PP - 1);
        t[tx][kk]      = src[(size_t)row * PP + c0];
        t[tx + 32][kk] = src[(size_t)row * PP + c1];
    }
    __syncthreads();
    hf* dst = out + (size_t)bh * SS * SS;
    for (int qq = ty; qq < 32; qq += 8)
        dst[(size_t)(q0 + qq) * SS + k0 + tx] = t[qq + 31 - tx][tx];
}

// ---------------- embedding / LN / softmax ----------------------------------------
__global__ __launch_bounds__(256) void embed_ln(
    const int* __restrict__ ids, const int* __restrict__ segs,
    const float* __restrict__ mask, const float* __restrict__ tok,
    const float* __restrict__ seg, const float* __restrict__ g,
    const float* __restrict__ b)
{
    int row = blockIdx.x, tid = threadIdx.x;
    const float* t  = tok + (size_t)ids[row]  * DD;
    const float* sg = seg + (size_t)segs[row] * DD;
    float x[4]; float s = 0.f;
    #pragma unroll
    for (int i = 0; i < 4; i++) { int c = tid + i*256; x[i] = t[c] + sg[c]; s += x[i]; }
    __shared__ float red[256];
    red[tid] = s; __syncthreads();
    for (int o = 128; o > 0; o >>= 1) { if (tid < o) red[tid] += red[tid+o]; __syncthreads(); }
    float m = red[0] * (1.f / DD); __syncthreads();
    s = 0.f;
    #pragma unroll
    for (int i = 0; i < 4; i++) { float d = x[i] - m; s += d*d; }
    red[tid] = s; __syncthreads();
    for (int o = 128; o > 0; o >>= 1) { if (tid < o) red[tid] += red[tid+o]; __syncthreads(); }
    float inv = rsqrtf(red[0] * (1.f / DD) + 1e-12f);
    float mk = mask[row];
    #pragma unroll
    for (int i = 0; i < 4; i++) {
        int c = tid + i*256;
        float y = ((x[i] - m) * inv * g[c] + b[c]) * mk;
        size_t o = (size_t)row * DD + c;
        g_h[o] = y; hb[o] = __float2half(y);
    }
}

__global__ __launch_bounds__(256) void add_ln(
    const float* __restrict__ base, const float* __restrict__ addv,
    const float* __restrict__ g, const float* __restrict__ b,
    float* __restrict__ out)
{
    int row = blockIdx.x, tid = threadIdx.x;
    size_t off = (size_t)row * DD;
    float x[4]; float s = 0.f;
    #pragma unroll
    for (int i = 0; i < 4; i++) { int c = tid + i*256; x[i] = base[off+c] + addv[off+c]; s += x[i]; }
    __shared__ float red[256];
    red[tid] = s; __syncthreads();
    for (int o = 128; o > 0; o >>= 1) { if (tid < o) red[tid] += red[tid+o]; __syncthreads(); }
    float m = red[0] * (1.f / DD); __syncthreads();
    s = 0.f;
    #pragma unroll
    for (int i = 0; i < 4; i++) { float d = x[i] - m; s += d*d; }
    red[tid] = s; __syncthreads();
    for (int o = 128; o > 0; o >>= 1) { if (tid < o) red[tid] += red[tid+o]; __syncthreads(); }
    float inv = rsqrtf(red[0] * (1.f / DD) + 1e-12f);
    #pragma unroll
    for (int i = 0; i < 4; i++) {
        int c = tid + i*256;
        float y = (x[i] - m) * inv * g[c] + b[c];
        out[off + c] = y; hb[off + c] = __float2half(y);
    }
}

__global__ __launch_bounds__(256) void softmax_rel(
    const hf* __restrict__ att, const hf* __restrict__ c2p,
    const hf* __restrict__ p2cT, const float* __restrict__ mask)
{
    int bh = blockIdx.y, q = blockIdx.x, b = bh / HH;
    int tid = threadIdx.x;
    size_t rowOff = ((size_t)bh * SS + q) * SS;
    const float scale = 0.07216878364870323f; // 1/sqrt(64*3)

    float v[4];
    #pragma unroll
    for (int t = 0; t < 4; t++) {
        int k = tid + t * 256;
        int idx = min(max(q - k + SPAN_, 0), PP - 1);
        float s = __half2float(att[rowOff + k])
                + __half2float(c2p[((size_t)bh * SS + q) * PP + idx])
                + __half2float(p2cT[rowOff + k]);
        v[t] = s * scale + (1.f - mask[b * SS + k]) * -1e9f;
    }
    __shared__ float red[256];
    float m = fmaxf(fmaxf(v[0], v[1]), fmaxf(v[2], v[3]));
    red[tid] = m; __syncthreads();
    for (int o = 128; o > 0; o >>= 1) { if (tid < o) red[tid] = fmaxf(red[tid], red[tid+o]); __syncthreads(); }
    m = red[0]; __syncthreads();
    float s = 0.f;
    #pragma unroll
    for (int t = 0; t < 4; t++) { v[t] = expf(v[t] - m); s += v[t]; }
    red[tid] = s; __syncthreads();
    for (int o = 128; o > 0; o >>= 1) { if (tid < o) red[tid] += red[tid+o]; __syncthreads(); }
    float inv = 1.f / red[0];
    #pragma unroll
    for (int t = 0; t < 4; t++)
        prb[rowOff + tid + t * 256] = __float2half(v[t] * inv);
}

// ---------------- host --------------------------------------------------------------
extern "C" void kernel_launch(void* const* d_in, const int* in_sizes, int n_in,
                              void* d_out, int out_size)
{
    const int*   ids  = (const int*)d_in[0];
    const int*   segs = (const int*)d_in[1];
    const float* mask = (const float*)d_in[2];
    const float* tok  = (const float*)d_in[3];
    const float* seg  = (const float*)d_in[4];
    const float* elg  = (const float*)d_in[5];
    const float* elb  = (const float*)d_in[6];
    const float* rel  = (const float*)d_in[7];
    const float* Wq = (const float*)d_in[8],  *bq = (const float*)d_in[9];
    const float* Wk = (const float*)d_in[10], *bk = (const float*)d_in[11];
    const float* Wv = (const float*)d_in[12], *bv = (const float*)d_in[13];
    const float* Wo = (const float*)d_in[14], *bo = (const float*)d_in[15];
    const float* l1g = (const float*)d_in[16], *l1b = (const float*)d_in[17];
    const float* W1 = (const float*)d_in[18], *b1 = (const float*)d_in[19];
    const float* W2 = (const float*)d_in[20], *b2 = (const float*)d_in[21];
    const float* l2g = (const float*)d_in[22], *l2b = (const float*)d_in[23];

    float *h, *t2, *qb3, *pb2;
    cudaGetSymbolAddress((void**)&h,   g_h);
    cudaGetSymbolAddress((void**)&t2,  g_t2);
    cudaGetSymbolAddress((void**)&qb3, qkv_bias);
    cudaGetSymbolAddress((void**)&pb2, pos_bias);

    hf *hh,*qkv,*cx,*ff,*rl,*pos;
    hf *wqkv,*wpos,*wo_,*w1_,*w2_;
    hf *vt,*pr,*s1,*c2p,*p2c,*p2cT;
    cudaGetSymbolAddress((void**)&hh,  hb);
    cudaGetSymbolAddress((void**)&qkv, qkvb);  cudaGetSymbolAddress((void**)&cx, cxb);
    cudaGetSymbolAddress((void**)&ff,  ffb);   cudaGetSymbolAddress((void**)&rl, rlb);
    cudaGetSymbolAddress((void**)&pos, posb);
    cudaGetSymbolAddress((void**)&wqkv, wqkvt); cudaGetSymbolAddress((void**)&wpos, wpost);
    cudaGetSymbolAddress((void**)&wo_, wot);
    cudaGetSymbolAddress((void**)&w1_, w1t);   cudaGetSymbolAddress((void**)&w2_, w2t);
    cudaGetSymbolAddress((void**)&vt, vtb);    cudaGetSymbolAddress((void**)&pr, prb);
    cudaGetSymbolAddress((void**)&s1, s1b);    cudaGetSymbolAddress((void**)&c2p, c2pb);
    cudaGetSymbolAddress((void**)&p2c, p2cb);  cudaGetSymbolAddress((void**)&p2cT, p2cTb);

    const int SM128 = 3 * (128*128 + 128*128);   // 98304
    const int SM64  = 3 * (128*128 + 64*128);    // 73728
    cudaFuncSetAttribute(gemm_mma<128,0>, cudaFuncAttributeMaxDynamicSharedMemorySize, SM128);
    cudaFuncSetAttribute(gemm_mma<128,1>, cudaFuncAttributeMaxDynamicSharedMemorySize, SM128);
    cudaFuncSetAttribute(gemm_mma<64,0>,  cudaFuncAttributeMaxDynamicSharedMemorySize, SM64);

    embed_ln<<<BS, 256>>>(ids, segs, mask, tok, seg, elg, elb);
    cvt_fp16<<<512, 256>>>(rel, rl, (size_t)PP * DD);

    dim3 tb(32, 8);
    const ll S2 = (ll)SS * SS;
    const ll SQ = (ll)SS * 3 * DD;   // qkv row-batch stride

    for (int l = 0; l < LL; l++) {
        const float* wq = Wq + (size_t)l*DD*DD;  const float* bq_ = bq + (size_t)l*DD;
        const float* wk = Wk + (size_t)l*DD*DD;  const float* bk_ = bk + (size_t)l*DD;
        const float* wv = Wv + (size_t)l*DD*DD;  const float* bv_ = bv + (size_t)l*DD;
        const float* wo = Wo + (size_t)l*DD*DD;  const float* bo_ = bo + (size_t)l*DD;
        const float* w1 = W1 + (size_t)l*DD*FFD; const float* b1_ = b1 + (size_t)l*FFD;
        const float* w2 = W2 + (size_t)l*FFD*DD; const float* b2_ = b2 + (size_t)l*DD;
        const float* g1 = l1g + (size_t)l*DD;    const float* be1 = l1b + (size_t)l*DD;
        const float* g2 = l2g + (size_t)l*DD;    const float* be2 = l2b + (size_t)l*DD;

        transpose_cvt<<<dim3(32, 32),  tb>>>(wq, wqkv,            DD, DD);
        transpose_cvt<<<dim3(32, 32),  tb>>>(wk, wqkv + DD*DD,    DD, DD);
        transpose_cvt<<<dim3(32, 32),  tb>>>(wv, wqkv + 2*DD*DD,  DD, DD);
        transpose_cvt<<<dim3(32, 32),  tb>>>(wk, wpos,            DD, DD);
        transpose_cvt<<<dim3(32, 32),  tb>>>(wq, wpos + DD*DD,    DD, DD);
        transpose_cvt<<<dim3(32, 32),  tb>>>(wo, wo_, DD, DD);
        transpose_cvt<<<dim3(128, 32), tb>>>(w1, w1_, DD, FFD);
        transpose_cvt<<<dim3(32, 128), tb>>>(w2, w2_, FFD, DD);
        concat_bias<<<4, 256>>>(bq_, bk_, bv_, pb2, qb3);

        // fused QKV projection: [BS x 3072]
        gemm_mma<128,0><<<dim3(24,32,1), 256, SM128>>>(hh,DD,0,0, wqkv,DD,0,0,
            (float*)0, qkv, 3*DD,0,0, DD, qb3);
        // fused pos projections: [PP x 2048] = rel @ [wk; wq]
        gemm_mma<128,0><<<dim3(16,8,1), 256, SM128>>>(rl,DD,0,0, wpos,DD,0,0,
            (float*)0, pos, 2*DD,0,0, DD, pb2);

        const hf* q = qkv;
        const hf* k = qkv + DD;
        const hf* v = qkv + 2*DD;
        const hf* pk = pos;
        const hf* pq = pos + DD;

        // attention scores
        gemm_mma<128,0><<<dim3(8,8,64), 256, SM128>>>(q,3*DD,SQ,64, k,3*DD,SQ,64,
            (float*)0, s1, SS,16*S2,S2, 64, (const float*)0);
        gemm_mma<128,0><<<dim3(8,8,64), 256, SM128>>>(q,3*DD,SQ,64, pk,2*DD,0,64,
            (float*)0, c2p, PP,16*S2,S2, 64, (const float*)0);
        gemm_mma<128,0><<<dim3(8,8,64), 256, SM128>>>(k,3*DD,SQ,64, pq,2*DD,0,64,
            (float*)0, p2c, PP,16*S2,S2, 64, (const float*)0);

        p2c_remap<<<dim3(32,32,64), tb>>>(p2c, p2cT);
        softmax_rel<<<dim3(SS, 64), 256>>>(s1, c2p, p2cT, mask);
        vt_cvt<<<dim3(32,2,64), tb>>>(v, 3*DD, vt);

        // ctx = probs @ V
        gemm_mma<64,0><<<dim3(1,8,64), 256, SM64>>>(pr,SS,16*S2,S2, vt,SS,(ll)16*64*SS,(ll)64*SS,
            (float*)0, cx, DD,(ll)SS*DD,64, SS, (const float*)0);

        // output projection + LN
        gemm_mma<128,0><<<dim3(8,32,1), 256, SM128>>>(cx,DD,0,0, wo_,DD,0,0,
            t2, (hf*)0, DD,0,0, DD, bo_);
        add_ln<<<BS, 256>>>(h, t2, g1, be1, h);

        // FFN
        gemm_mma<128,1><<<dim3(32,32,1), 256, SM128>>>(hh,DD,0,0, w1_,DD,0,0,
            (float*)0, ff, FFD,0,0, DD, b1_);
        gemm_mma<128,0><<<dim3(8,32,1), 256, SM128>>>(ff,FFD,0,0, w2_,FFD,0,0,
            t2, (hf*)0, DD,0,0, FFD, b2_);
        add_ln<<<BS, 256>>>(h, t2, g2, be2, h);
    }

    cudaMemcpyAsync(d_out, h, (size_t)BS * DD * sizeof(float),
                    cudaMemcpyDeviceToDevice);
}

// round 10
// speedup vs baseline: 1.2301x; 1.0816x over previous
#include <cuda_runtime.h>
#include <cuda_fp16.h>
#include <math.h>
#include <stdint.h>

#define BB 4
#define SS 1024
#define DD 1024
#define HH 16
#define DHH 64
#define FFD 4096
#define LL 4
#define PP 1024
#define SPAN_ 512
#define BS (BB*SS)

typedef long long ll;
typedef __half hf;

// ---------------- scratch ------------------------------------------------------
__device__ float g_h [BS*DD];
__device__ float g_t2[BS*DD];
__device__ float qkv_bias[4*3*DD];
__device__ float pos_bias[4*2*DD];

__device__ hf hb    [BS*DD];
__device__ hf qkvb  [(size_t)BS*3*DD];
__device__ hf cxb   [BS*DD];
__device__ hf ffb   [(size_t)BS*FFD];
__device__ hf rlb   [PP*DD];
__device__ hf posb  [(size_t)PP*2*DD];
__device__ hf wqkvt [(size_t)4*3*DD*DD];
__device__ hf wpost [(size_t)4*2*DD*DD];
__device__ hf wot   [(size_t)4*DD*DD];
__device__ hf w1t   [(size_t)4*FFD*DD];
__device__ hf w2t   [(size_t)4*DD*FFD];
__device__ hf vtb   [(size_t)BB*HH*DHH*SS];
__device__ hf prb   [(size_t)BB*HH*SS*SS];
__device__ hf s1b   [(size_t)BB*HH*SS*SS];
__device__ hf c2pb  [(size_t)BB*HH*SS*PP];
__device__ hf p2cb  [(size_t)BB*HH*SS*PP];
__device__ hf p2cTb [(size_t)BB*HH*SS*SS];

// ---------------- helpers ------------------------------------------------------
__device__ __forceinline__ uint32_t smem_u32(const void* p) {
    uint32_t a;
    asm("{ .reg .u64 t; cvta.to.shared.u64 t, %1; cvt.u32.u64 %0, t; }" : "=r"(a) : "l"(p));
    return a;
}
__device__ __forceinline__ void cpa16(uint32_t dst, const void* src) {
    asm volatile("cp.async.cg.shared.global [%0], [%1], 16;" :: "r"(dst), "l"(src));
}
__device__ __forceinline__ void cpa_commit() { asm volatile("cp.async.commit_group;" ::: "memory"); }

__device__ __forceinline__ void ldm4(uint32_t* r, uint32_t addr) {
    asm volatile("ldmatrix.sync.aligned.m8n8.x4.shared.b16 {%0,%1,%2,%3}, [%4];"
                 : "=r"(r[0]), "=r"(r[1]), "=r"(r[2]), "=r"(r[3]) : "r"(addr));
}
__device__ __forceinline__ void mma16816(float* d, const uint32_t* a, const uint32_t* b) {
    asm volatile("mma.sync.aligned.m16n8k16.row.col.f32.f16.f16.f32 "
                 "{%0,%1,%2,%3}, {%4,%5,%6,%7}, {%8,%9}, {%0,%1,%2,%3};"
                 : "+f"(d[0]), "+f"(d[1]), "+f"(d[2]), "+f"(d[3])
                 : "r"(a[0]), "r"(a[1]), "r"(a[2]), "r"(a[3]), "r"(b[0]), "r"(b[1]));
}

// ---------------- fp16 mma.sync GEMM, 3-stage, 1 sync/chunk (R9-validated) -------
template <int NT, int ACT>
__global__ void __launch_bounds__(256) gemm_mma(
    const hf* __restrict__ A, int ldA, ll aSB, ll aSH,
    const hf* __restrict__ B, int ldB, ll bSB, ll bSH,
    float* __restrict__ C, hf* __restrict__ Ch,
    int ldC, ll cSB, ll cSH,
    int K, const float* __restrict__ bias)
{
    constexpr int ABY = 128 * 128;
    constexpr int BBY = NT * 128;
    constexpr int STAGE = ABY + BBY;
    constexpr int MT = (NT == 128) ? 4 : 2;
    constexpr int JT = 4;

    extern __shared__ char smem_raw[];
    uint32_t sbase = smem_u32(smem_raw);

    int tid = threadIdx.x, lane = tid & 31, wid = tid >> 5;
    int z = blockIdx.z;

    int warpM, warpN;
    if (NT == 128) { warpM = (wid & 1) * 64; warpN = (wid >> 1) * 32; }
    else           { warpM = (wid & 3) * 32; warpN = (wid >> 2) * 32; }

    const hf* Ab = A + (size_t)((ll)(z >> 4) * aSB + (ll)(z & 15) * aSH)
                     + (size_t)blockIdx.y * 128 * ldA;
    const hf* Bb = B + (size_t)((ll)(z >> 4) * bSB + (ll)(z & 15) * bSH)
                     + (size_t)blockIdx.x * NT * ldB;

    int NC = K >> 6;

    auto load_chunk = [&](int cn, int stage) {
        const hf* Ap = Ab + cn * 64;
        const hf* Bp = Bb + cn * 64;
        uint32_t Ad = sbase + stage * STAGE;
        uint32_t Bd = Ad + ABY;
        #pragma unroll
        for (int i = 0; i < 4; i++) {
            int idx = tid + i * 256;
            int r = idx >> 3, c = idx & 7;
            cpa16(Ad + r * 128 + ((c ^ (r & 7)) << 4), Ap + (size_t)r * ldA + c * 8);
        }
        #pragma unroll
        for (int i = 0; i < NT / 32; i++) {
            int idx = tid + i * 256;
            int r = idx >> 3, c = idx & 7;
            cpa16(Bd + r * 128 + ((c ^ (r & 7)) << 4), Bp + (size_t)r * ldB + c * 8);
        }
        cpa_commit();
    };

    float acc[MT][JT][4];
    #pragma unroll
    for (int i = 0; i < MT; i++)
        #pragma unroll
        for (int j = 0; j < JT; j++)
            #pragma unroll
            for (int e = 0; e < 4; e++) acc[i][j][e] = 0.f;

    load_chunk(0, 0);
    if (NC > 1) load_chunk(1, 1);

    for (int c = 0; c < NC; c++) {
        if (c + 1 < NC) asm volatile("cp.async.wait_group 1;" ::: "memory");
        else            asm volatile("cp.async.wait_group 0;" ::: "memory");
        __syncthreads();

        uint32_t Abuf = sbase + (c % 3) * STAGE;
        uint32_t Bbuf = Abuf + ABY;
        #pragma unroll
        for (int ks = 0; ks < 4; ks++) {
            uint32_t a[MT][4], b[JT][2];
            #pragma unroll
            for (int i = 0; i < MT; i++) {
                int row = warpM + i * 16 + (lane & 15);
                int cc = ks * 2 + (lane >> 4);
                ldm4(a[i], Abuf + row * 128 + (((cc ^ (row & 7)) << 4)));
            }
            #pragma unroll
            for (int j = 0; j < JT / 2; j++) {
                int n = warpN + j * 16 + ((lane >> 4) << 3) + (lane & 7);
                int cc = ks * 2 + ((lane >> 3) & 1);
                uint32_t t[4];
                ldm4(t, Bbuf + n * 128 + (((cc ^ (n & 7)) << 4)));
                b[j*2][0] = t[0];   b[j*2][1] = t[1];
                b[j*2+1][0] = t[2]; b[j*2+1][1] = t[3];
            }
            #pragma unroll
            for (int i = 0; i < MT; i++)
                #pragma unroll
                for (int j = 0; j < JT; j++)
                    mma16816(acc[i][j], a[i], b[j]);
        }
        if (c + 2 < NC) load_chunk(c + 2, (c + 2) % 3);
    }

    ll cO = (ll)(z >> 4) * cSB + (ll)(z & 15) * cSH;
    int m0 = blockIdx.y * 128, n0 = blockIdx.x * NT;
    int quad = lane >> 2, l4 = lane & 3;

    #pragma unroll
    for (int i = 0; i < MT; i++) {
        int r0 = m0 + warpM + i * 16 + quad;
        #pragma unroll
        for (int j = 0; j < JT; j++) {
            int col = n0 + warpN + j * 8 + l4 * 2;
            float b0 = 0.f, b1 = 0.f;
            if (bias) { b0 = bias[col]; b1 = bias[col + 1]; }
            #pragma unroll
            for (int half = 0; half < 2; half++) {
                int row = r0 + half * 8;
                float v0 = acc[i][j][half*2 + 0] + b0;
                float v1 = acc[i][j][half*2 + 1] + b1;
                if (ACT) {
                    v0 = 0.5f * v0 * (1.f + erff(v0 * 0.70710678118654752f));
                    v1 = 0.5f * v1 * (1.f + erff(v1 * 0.70710678118654752f));
                }
                size_t base = (size_t)cO + (size_t)row * ldC + col;
                if (C) *(float2*)(C + base) = make_float2(v0, v1);
                if (Ch) *(__half2*)(Ch + base) =
                    __halves2half2(__float2half(v0), __float2half(v1));
            }
        }
    }
}

// ---------------- converters -----------------------------------------------------
__global__ __launch_bounds__(256) void cvt_fp16(
    const float* __restrict__ in, hf* __restrict__ out, size_t n)
{
    for (size_t i = blockIdx.x * 256ull + threadIdx.x; i < n; i += gridDim.x * 256ull)
        out[i] = __float2half(in[i]);
}

// per-layer bias concat, z = layer
__global__ void concat_bias(const float* bq, const float* bk, const float* bv,
                            float* out2, float* out3)
{
    int l = blockIdx.z;
    const float* a = bq + (size_t)l * DD;
    const float* b = bk + (size_t)l * DD;
    const float* c = bv + (size_t)l * DD;
    float* o3 = out3 + (size_t)l * 3 * DD;
    float* o2 = out2 + (size_t)l * 2 * DD;
    int i = blockIdx.x * 256 + threadIdx.x;
    if (i < DD) {
        o3[i] = a[i]; o3[i + DD] = b[i]; o3[i + 2*DD] = c[i];
        o2[i] = b[i]; o2[i + DD] = a[i];
    }
}

// in [K x N] fp32 -> out [N x K] fp16, z = layer with strides
__global__ void transpose_cvt(
    const float* __restrict__ in, ll inLS, hf* __restrict__ out, ll outLS,
    int K, int N)
{
    in  += (size_t)blockIdx.z * inLS;
    out += (size_t)blockIdx.z * outLS;
    __shared__ float t[32][33];
    int k0 = blockIdx.y * 32, n0 = blockIdx.x * 32;
    int tx = threadIdx.x, ty = threadIdx.y;
    for (int i = ty; i < 32; i += 8)
        t[i][tx] = in[(size_t)(k0 + i) * N + n0 + tx];
    __syncthreads();
    for (int i = ty; i < 32; i += 8)
        out[(size_t)(n0 + i) * K + k0 + tx] = __float2half(t[tx][i]);
}

// v fp16 (rows stride ldv) -> vt fp16 [(b*16+h)*64+d][s]
__global__ void vt_cvt(const hf* __restrict__ v, int ldv, hf* __restrict__ out)
{
    __shared__ hf t[32][33];
    int bh = blockIdx.z, b = bh >> 4, h = bh & 15;
    int s0 = blockIdx.x * 32, d0 = blockIdx.y * 32;
    int tx = threadIdx.x, ty = threadIdx.y;
    for (int i = ty; i < 32; i += 8)
        t[i][tx] = v[((size_t)b * SS + s0 + i) * ldv + h * 64 + d0 + tx];
    __syncthreads();
    for (int i = ty; i < 32; i += 8)
        out[((size_t)bh * 64 + d0 + i) * SS + s0 + tx] = t[tx][i];
}

// p2cT[bh][q][k] = p2c[bh][k][clip(q-k+512,0,1023)]
__global__ void p2c_remap(const hf* __restrict__ p2c, hf* __restrict__ out)
{
    __shared__ hf t[64][34];
    int bh = blockIdx.z;
    int q0 = blockIdx.y * 32, k0 = blockIdx.x * 32;
    int tx = threadIdx.x, ty = threadIdx.y;
    int base = q0 - k0 + SPAN_ - 31;
    const hf* src = p2c + (size_t)bh * SS * PP;
    for (int kk = ty; kk < 32; kk += 8) {
        int row = k0 + kk;
        int c0 = min(max(base + tx, 0), PP - 1);
        int c1 = min(max(base + tx + 32, 0), PP - 1);
        t[tx][kk]      = src[(size_t)row * PP + c0];
        t[tx + 32][kk] = src[(size_t)row * PP + c1];
    }
    __syncthreads();
    hf* dst = out + (size_t)bh * SS * SS;
    for (int qq = ty; qq < 32; qq += 8)
        dst[(size_t)(q0 + qq) * SS + k0 + tx] = t[qq + 31 - tx][tx];
}

// ---------------- embedding / LN ----------------------------------------------
__global__ __launch_bounds__(256) void embed_ln(
    const int* __restrict__ ids, const int* __restrict__ segs,
    const float* __restrict__ mask, const float* __restrict__ tok,
    const float* __restrict__ seg, const float* __restrict__ g,
    const float* __restrict__ b)
{
    int row = blockIdx.x, tid = threadIdx.x;
    const float* t  = tok + (size_t)ids[row]  * DD;
    const float* sg = seg + (size_t)segs[row] * DD;
    float x[4]; float s = 0.f;
    #pragma unroll
    for (int i = 0; i < 4; i++) { int c = tid + i*256; x[i] = t[c] + sg[c]; s += x[i]; }
    __shared__ float red[256];
    red[tid] = s; __syncthreads();
    for (int o = 128; o > 0; o >>= 1) { if (tid < o) red[tid] += red[tid+o]; __syncthreads(); }
    float m = red[0] * (1.f / DD); __syncthreads();
    s = 0.f;
    #pragma unroll
    for (int i = 0; i < 4; i++) { float d = x[i] - m; s += d*d; }
    red[tid] = s; __syncthreads();
    for (int o = 128; o > 0; o >>= 1) { if (tid < o) red[tid] += red[tid+o]; __syncthreads(); }
    float inv = rsqrtf(red[0] * (1.f / DD) + 1e-12f);
    float mk = mask[row];
    #pragma unroll
    for (int i = 0; i < 4; i++) {
        int c = tid + i*256;
        float y = ((x[i] - m) * inv * g[c] + b[c]) * mk;
        size_t o = (size_t)row * DD + c;
        g_h[o] = y; hb[o] = __float2half(y);
    }
}

__global__ __launch_bounds__(256) void add_ln(
    const float* __restrict__ base, const float* __restrict__ addv,
    const float* __restrict__ g, const float* __restrict__ b,
    float* __restrict__ out)
{
    int row = blockIdx.x, tid = threadIdx.x;
    size_t off = (size_t)row * DD;
    float x[4]; float s = 0.f;
    #pragma unroll
    for (int i = 0; i < 4; i++) { int c = tid + i*256; x[i] = base[off+c] + addv[off+c]; s += x[i]; }
    __shared__ float red[256];
    red[tid] = s; __syncthreads();
    for (int o = 128; o > 0; o >>= 1) { if (tid < o) red[tid] += red[tid+o]; __syncthreads(); }
    float m = red[0] * (1.f / DD); __syncthreads();
    s = 0.f;
    #pragma unroll
    for (int i = 0; i < 4; i++) { float d = x[i] - m; s += d*d; }
    red[tid] = s; __syncthreads();
    for (int o = 128; o > 0; o >>= 1) { if (tid < o) red[tid] += red[tid+o]; __syncthreads(); }
    float inv = rsqrtf(red[0] * (1.f / DD) + 1e-12f);
    #pragma unroll
    for (int i = 0; i < 4; i++) {
        int c = tid + i*256;
        float y = (x[i] - m) * inv * g[c] + b[c];
        out[off + c] = y; hb[off + c] = __float2half(y);
    }
}

// ---------------- warp-per-row softmax + relative-bias ------------------------
// block = 256 (8 warps = 8 rows); grid (SS/8, BB*HH)
__global__ __launch_bounds__(256) void softmax_rel(
    const hf* __restrict__ att, const hf* __restrict__ c2p,
    const hf* __restrict__ p2cT, const float* __restrict__ mask)
{
    int bh = blockIdx.y;
    int warp = threadIdx.x >> 5, lane = threadIdx.x & 31;
    int q = blockIdx.x * 8 + warp;
    int b = bh >> 4;
    size_t rowOff = ((size_t)bh * SS + q) * SS;
    const float scale = 0.07216878364870323f; // 1/sqrt(64*3)

    const __half2* s1r = (const __half2*)(att + rowOff);
    const __half2* p2r = (const __half2*)(p2cT + rowOff);
    const hf* c2r = c2p + ((size_t)bh * SS + q) * PP;
    const float* mk = mask + b * SS;

    float v[32];
    float mx = -1e30f;
    #pragma unroll
    for (int i = 0; i < 16; i++) {
        int k2 = lane + i * 32;
        int k = k2 * 2;
        float2 s = __half22float2(s1r[k2]);
        float2 p = __half22float2(p2r[k2]);
        int idx0 = min(max(q - k + SPAN_, 0), PP - 1);
        int idx1 = min(max(q - k - 1 + SPAN_, 0), PP - 1);
        float c0 = __half2float(c2r[idx0]);
        float c1 = __half2float(c2r[idx1]);
        float v0 = (s.x + c0 + p.x) * scale + (1.f - mk[k])     * -1e9f;
        float v1 = (s.y + c1 + p.y) * scale + (1.f - mk[k + 1]) * -1e9f;
        v[i*2] = v0; v[i*2+1] = v1;
        mx = fmaxf(mx, fmaxf(v0, v1));
    }
    #pragma unroll
    for (int o = 16; o > 0; o >>= 1) mx = fmaxf(mx, __shfl_xor_sync(0xFFFFFFFFu, mx, o));
    float sum = 0.f;
    #pragma unroll
    for (int i = 0; i < 32; i++) { v[i] = expf(v[i] - mx); sum += v[i]; }
    #pragma unroll
    for (int o = 16; o > 0; o >>= 1) sum += __shfl_xor_sync(0xFFFFFFFFu, sum, o);
    float inv = 1.f / sum;
    __half2* out = (__half2*)(prb + rowOff);
    #pragma unroll
    for (int i = 0; i < 16; i++) {
        int k2 = lane + i * 32;
        out[k2] = __floats2half2_rn(v[i*2] * inv, v[i*2+1] * inv);
    }
}

// ---------------- host --------------------------------------------------------------
extern "C" void kernel_launch(void* const* d_in, const int* in_sizes, int n_in,
                              void* d_out, int out_size)
{
    const int*   ids  = (const int*)d_in[0];
    const int*   segs = (const int*)d_in[1];
    const float* mask = (const float*)d_in[2];
    const float* tok  = (const float*)d_in[3];
    const float* seg  = (const float*)d_in[4];
    const float* elg  = (const float*)d_in[5];
    const float* elb  = (const float*)d_in[6];
    const float* rel  = (const float*)d_in[7];
    const float* Wq = (const float*)d_in[8],  *bq = (const float*)d_in[9];
    const float* Wk = (const float*)d_in[10], *bk = (const float*)d_in[11];
    const float* Wv = (const float*)d_in[12], *bv = (const float*)d_in[13];
    const float* Wo = (const float*)d_in[14], *bo = (const float*)d_in[15];
    const float* l1g = (const float*)d_in[16], *l1b = (const float*)d_in[17];
    const float* W1 = (const float*)d_in[18], *b1 = (const float*)d_in[19];
    const float* W2 = (const float*)d_in[20], *b2 = (const float*)d_in[21];
    const float* l2g = (const float*)d_in[22], *l2b = (const float*)d_in[23];

    float *h, *t2, *qb3, *pb2;
    cudaGetSymbolAddress((void**)&h,   g_h);
    cudaGetSymbolAddress((void**)&t2,  g_t2);
    cudaGetSymbolAddress((void**)&qb3, qkv_bias);
    cudaGetSymbolAddress((void**)&pb2, pos_bias);

    hf *hh,*qkv,*cx,*ff,*rl,*pos;
    hf *wqkv,*wpos,*wo_,*w1_,*w2_;
    hf *vt,*pr,*s1,*c2p,*p2c,*p2cT;
    cudaGetSymbolAddress((void**)&hh,  hb);
    cudaGetSymbolAddress((void**)&qkv, qkvb);  cudaGetSymbolAddress((void**)&cx, cxb);
    cudaGetSymbolAddress((void**)&ff,  ffb);   cudaGetSymbolAddress((void**)&rl, rlb);
    cudaGetSymbolAddress((void**)&pos, posb);
    cudaGetSymbolAddress((void**)&wqkv, wqkvt); cudaGetSymbolAddress((void**)&wpos, wpost);
    cudaGetSymbolAddress((void**)&wo_, wot);
    cudaGetSymbolAddress((void**)&w1_, w1t);   cudaGetSymbolAddress((void**)&w2_, w2t);
    cudaGetSymbolAddress((void**)&vt, vtb);    cudaGetSymbolAddress((void**)&pr, prb);
    cudaGetSymbolAddress((void**)&s1, s1b);    cudaGetSymbolAddress((void**)&c2p, c2pb);
    cudaGetSymbolAddress((void**)&p2c, p2cb);  cudaGetSymbolAddress((void**)&p2cT, p2cTb);

    const int SM128 = 3 * (128*128 + 128*128);   // 98304
    const int SM64  = 3 * (128*128 + 64*128);    // 73728
    cudaFuncSetAttribute(gemm_mma<128,0>, cudaFuncAttributeMaxDynamicSharedMemorySize, SM128);
    cudaFuncSetAttribute(gemm_mma<128,1>, cudaFuncAttributeMaxDynamicSharedMemorySize, SM128);
    cudaFuncSetAttribute(gemm_mma<64,0>,  cudaFuncAttributeMaxDynamicSharedMemorySize, SM64);

    embed_ln<<<BS, 256>>>(ids, segs, mask, tok, seg, elg, elb);
    cvt_fp16<<<512, 256>>>(rel, rl, (size_t)PP * DD);

    dim3 tb(32, 8);
    const ll DD2  = (ll)DD * DD;
    const ll S2 = (ll)SS * SS;
    const ll SQ = (ll)SS * 3 * DD;

    // ---- all weight transposes + bias concats, once, z = layer ----
    transpose_cvt<<<dim3(32,32,4),  tb>>>(Wq, DD2, wqkv,          3*DD2, DD, DD);
    transpose_cvt<<<dim3(32,32,4),  tb>>>(Wk, DD2, wqkv + DD2,    3*DD2, DD, DD);
    transpose_cvt<<<dim3(32,32,4),  tb>>>(Wv, DD2, wqkv + 2*DD2,  3*DD2, DD, DD);
    transpose_cvt<<<dim3(32,32,4),  tb>>>(Wk, DD2, wpos,          2*DD2, DD, DD);
    transpose_cvt<<<dim3(32,32,4),  tb>>>(Wq, DD2, wpos + DD2,    2*DD2, DD, DD);
    transpose_cvt<<<dim3(32,32,4),  tb>>>(Wo, DD2, wo_,           DD2,   DD, DD);
    transpose_cvt<<<dim3(128,32,4), tb>>>(W1, (ll)DD*FFD, w1_, (ll)FFD*DD, DD, FFD);
    transpose_cvt<<<dim3(32,128,4), tb>>>(W2, (ll)FFD*DD, w2_, (ll)DD*FFD, FFD, DD);
    concat_bias<<<dim3(4,1,4), 256>>>(bq, bk, bv, pb2, qb3);

    for (int l = 0; l < LL; l++) {
        const hf* wqkvL = wqkv + (size_t)l * 3 * DD2;
        const hf* wposL = wpos + (size_t)l * 2 * DD2;
        const hf* woL   = wo_  + (size_t)l * DD2;
        const hf* w1L   = w1_  + (size_t)l * FFD * DD;
        const hf* w2L   = w2_  + (size_t)l * DD * FFD;
        const float* qb3L = qb3 + (size_t)l * 3 * DD;
        const float* pb2L = pb2 + (size_t)l * 2 * DD;
        const float* bo_ = bo + (size_t)l*DD;
        const float* b1_ = b1 + (size_t)l*FFD;
        const float* b2_ = b2 + (size_t)l*DD;
        const float* g1 = l1g + (size_t)l*DD;    const float* be1 = l1b + (size_t)l*DD;
        const float* g2 = l2g + (size_t)l*DD;    const float* be2 = l2b + (size_t)l*DD;

        // fused QKV projection: [BS x 3072]
        gemm_mma<128,0><<<dim3(24,32,1), 256, SM128>>>(hh,DD,0,0, wqkvL,DD,0,0,
            (float*)0, qkv, 3*DD,0,0, DD, qb3L);
        // fused pos projections: [PP x 2048]
        gemm_mma<128,0><<<dim3(16,8,1), 256, SM128>>>(rl,DD,0,0, wposL,DD,0,0,
            (float*)0, pos, 2*DD,0,0, DD, pb2L);

        const hf* q = qkv;
        const hf* k = qkv + DD;
        const hf* v = qkv + 2*DD;
        const hf* pk = pos;
        const hf* pq = pos + DD;

        // attention scores
        gemm_mma<128,0><<<dim3(8,8,64), 256, SM128>>>(q,3*DD,SQ,64, k,3*DD,SQ,64,
            (float*)0, s1, SS,16*S2,S2, 64, (const float*)0);
        gemm_mma<128,0><<<dim3(8,8,64), 256, SM128>>>(q,3*DD,SQ,64, pk,2*DD,0,64,
            (float*)0, c2p, PP,16*S2,S2, 64, (const float*)0);
        gemm_mma<128,0><<<dim3(8,8,64), 256, SM128>>>(k,3*DD,SQ,64, pq,2*DD,0,64,
            (float*)0, p2c, PP,16*S2,S2, 64, (const float*)0);

        p2c_remap<<<dim3(32,32,64), tb>>>(p2c, p2cT);
        softmax_rel<<<dim3(SS/8, 64), 256>>>(s1, c2p, p2cT, mask);
        vt_cvt<<<dim3(32,2,64), tb>>>(v, 3*DD, vt);

        // ctx = probs @ V
        gemm_mma<64,0><<<dim3(1,8,64), 256, SM64>>>(pr,SS,16*S2,S2, vt,SS,(ll)16*64*SS,(ll)64*SS,
            (float*)0, cx, DD,(ll)SS*DD,64, SS, (const float*)0);

        // output projection + LN
        gemm_mma<128,0><<<dim3(8,32,1), 256, SM128>>>(cx,DD,0,0, woL,DD,0,0,
            t2, (hf*)0, DD,0,0, DD, bo_);
        add_ln<<<BS, 256>>>(h, t2, g1, be1, h);

        // FFN
        gemm_mma<128,1><<<dim3(32,32,1), 256, SM128>>>(hh,DD,0,0, w1L,DD,0,0,
            (float*)0, ff, FFD,0,0, DD, b1_);
        gemm_mma<128,0><<<dim3(8,32,1), 256, SM128>>>(ff,FFD,0,0, w2L,FFD,0,0,
            t2, (hf*)0, DD,0,0, FFD, b2_);
        add_ln<<<BS, 256>>>(h, t2, g2, be2, h);
    }

    cudaMemcpyAsync(d_out, h, (size_t)BS * DD * sizeof(float),
                    cudaMemcpyDeviceToDevice);
}